// round 5
// baseline (speedup 1.0000x reference)
#include <cuda_runtime.h>
#include <cuda_bf16.h>

// Problem constants
#define BATCH 2
#define SEQ   2048
#define CDIM  1024
#define HEADS 16
#define HDIM  64
#define QKV_N (3*CDIM)
#define MROWS (BATCH*SEQ)          // 4096
#define ATT_SCALE 0.125f           // 64^-0.5

// Scratch (device globals; no allocation allowed)
__device__ float g_q[BATCH*HEADS*SEQ*HDIM];   // [B,H,N,D], pre-scaled by ATT_SCALE
__device__ float g_k[BATCH*HEADS*SEQ*HDIM];
__device__ float g_v[BATCH*HEADS*SEQ*HDIM];
__device__ float g_att[BATCH*SEQ*CDIM];       // [B,N,C] attention output

// ---------------------------------------------------------------------------
// Kernel 1: QKV GEMM.  X[4096,1024] @ Wqkv[1024,3072] -> scatter to q/k/v.
// 64x64 tile, BK=16, 256 threads, 4x4 per thread.
// ---------------------------------------------------------------------------
__global__ __launch_bounds__(256) void qkv_gemm(const float* __restrict__ X,
                                                const float* __restrict__ W) {
    __shared__ float As[16][68];   // As[k][m]
    __shared__ float Bs[16][68];   // Bs[k][n]
    const int tid = threadIdx.x;
    const int tx = tid & 15, ty = tid >> 4;
    const int row0 = blockIdx.y * 64;
    const int col0 = blockIdx.x * 64;

    const int am = tid >> 2;           // 0..63
    const int ak = (tid & 3) * 4;      // 0,4,8,12
    const int bk = tid >> 4;           // 0..15
    const int bn = (tid & 15) * 4;     // 0..60

    float acc[4][4] = {};

    for (int k0 = 0; k0 < CDIM; k0 += 16) {
        float4 a = *(const float4*)&X[(row0 + am) * CDIM + k0 + ak];
        As[ak + 0][am] = a.x; As[ak + 1][am] = a.y;
        As[ak + 2][am] = a.z; As[ak + 3][am] = a.w;
        *(float4*)&Bs[bk][bn] = *(const float4*)&W[(k0 + bk) * QKV_N + col0 + bn];
        __syncthreads();
#pragma unroll
        for (int k = 0; k < 16; k++) {
            float4 ra = *(float4*)&As[k][ty * 4];
            float4 rb = *(float4*)&Bs[k][tx * 4];
            acc[0][0] += ra.x * rb.x; acc[0][1] += ra.x * rb.y; acc[0][2] += ra.x * rb.z; acc[0][3] += ra.x * rb.w;
            acc[1][0] += ra.y * rb.x; acc[1][1] += ra.y * rb.y; acc[1][2] += ra.y * rb.z; acc[1][3] += ra.y * rb.w;
            acc[2][0] += ra.z * rb.x; acc[2][1] += ra.z * rb.y; acc[2][2] += ra.z * rb.z; acc[2][3] += ra.z * rb.w;
            acc[3][0] += ra.w * rb.x; acc[3][1] += ra.w * rb.y; acc[3][2] += ra.w * rb.z; acc[3][3] += ra.w * rb.w;
        }
        __syncthreads();
    }

#pragma unroll
    for (int i = 0; i < 4; i++) {
        const int r = row0 + ty * 4 + i;
        const int b = r >> 11;             // r / SEQ
        const int n = r & (SEQ - 1);
#pragma unroll
        for (int j = 0; j < 4; j++) {
            const int c = col0 + tx * 4 + j;
            const int sel = c >> 10;       // 0=q,1=k,2=v
            const int rr  = c & 1023;
            const int h   = rr >> 6;
            const int d   = rr & 63;
            const int idx = ((b * HEADS + h) * SEQ + n) * HDIM + d;
            const float v = acc[i][j];
            if (sel == 0)      g_q[idx] = v * ATT_SCALE;
            else if (sel == 1) g_k[idx] = v;
            else               g_v[idx] = v;
        }
    }
}

// ---------------------------------------------------------------------------
// Kernel 2: flash attention (fp32, online softmax).
// Block: 64 query rows of one (b,h); loop over 32 key tiles of 64.
// Smem: Qst[d][r], KV (K as [d][c], then V as [k][d]), Sst[c][r]  (pad 68).
// ---------------------------------------------------------------------------
__global__ __launch_bounds__(256) void attn_kernel() {
    extern __shared__ float sm[];
    float* Qst  = sm;                 // 64*68
    float* KV   = sm + 64 * 68;       // 64*68
    float* Sst  = sm + 2 * 64 * 68;   // 64*68
    float* mrow = sm + 3 * 64 * 68;   // 64
    float* lrow = mrow + 64;          // 64
    float* frow = lrow + 64;          // 64
    float* red  = frow + 64;          // 64*4

    const int tid = threadIdx.x;
    const int tx = tid & 15, ty = tid >> 4;
    const int bh = blockIdx.y;                // b*HEADS + h
    const int q0 = blockIdx.x * 64;

    const float* Qg  = g_q + (bh * SEQ + q0) * HDIM;
    const float* Kg0 = g_k + bh * SEQ * HDIM;
    const float* Vg0 = g_v + bh * SEQ * HDIM;

    if (tid < 64) { mrow[tid] = -1e30f; lrow[tid] = 0.f; }

    // Load Q tile transposed: Qst[d*68 + r]
    {
        const int r  = tid >> 2;
        const int db = (tid & 3) * 16;
#pragma unroll
        for (int i = 0; i < 4; i++) {
            const int d = db + i * 4;
            float4 v = *(const float4*)&Qg[r * HDIM + d];
            Qst[(d + 0) * 68 + r] = v.x;
            Qst[(d + 1) * 68 + r] = v.y;
            Qst[(d + 2) * 68 + r] = v.z;
            Qst[(d + 3) * 68 + r] = v.w;
        }
    }

    float o[4][4] = {};
    const int r0 = ty * 4, c0 = tx * 4;

    for (int kt = 0; kt < SEQ / 64; kt++) {
        const float* Kg = Kg0 + kt * 64 * HDIM;
        const float* Vg = Vg0 + kt * 64 * HDIM;

        // Load K tile transposed: KV[d*68 + c]
        {
            const int c  = tid >> 2;
            const int db = (tid & 3) * 16;
#pragma unroll
            for (int i = 0; i < 4; i++) {
                const int d = db + i * 4;
                float4 v = *(const float4*)&Kg[c * HDIM + d];
                KV[(d + 0) * 68 + c] = v.x;
                KV[(d + 1) * 68 + c] = v.y;
                KV[(d + 2) * 68 + c] = v.z;
                KV[(d + 3) * 68 + c] = v.w;
            }
        }
        __syncthreads();

        // S = Q @ K^T  (Q pre-scaled); write Sst[c*68 + r]
        {
            float s[4][4] = {};
#pragma unroll 8
            for (int k = 0; k < 64; k++) {
                float4 rq = *(float4*)&Qst[k * 68 + r0];
                float4 rk = *(float4*)&KV [k * 68 + c0];
                s[0][0] += rq.x * rk.x; s[0][1] += rq.x * rk.y; s[0][2] += rq.x * rk.z; s[0][3] += rq.x * rk.w;
                s[1][0] += rq.y * rk.x; s[1][1] += rq.y * rk.y; s[1][2] += rq.y * rk.z; s[1][3] += rq.y * rk.w;
                s[2][0] += rq.z * rk.x; s[2][1] += rq.z * rk.y; s[2][2] += rq.z * rk.z; s[2][3] += rq.z * rk.w;
                s[3][0] += rq.w * rk.x; s[3][1] += rq.w * rk.y; s[3][2] += rq.w * rk.z; s[3][3] += rq.w * rk.w;
            }
#pragma unroll
            for (int j = 0; j < 4; j++)
#pragma unroll
                for (int i = 0; i < 4; i++)
                    Sst[(c0 + j) * 68 + (r0 + i)] = s[i][j];
        }
        __syncthreads();

        // Load V tile (plain [k][d]) into KV, plus per-row max partials
        {
            const int kr = tid >> 2;
            const int db = (tid & 3) * 16;
#pragma unroll
            for (int i = 0; i < 4; i++)
                *(float4*)&KV[kr * 68 + db + i * 4] =
                    *(const float4*)&Vg[kr * HDIM + db + i * 4];
        }
        {
            const int r = tid & 63, qtr = tid >> 6;
            float mx = -1e30f;
#pragma unroll
            for (int t = 0; t < 16; t++)
                mx = fmaxf(mx, Sst[(qtr * 16 + t) * 68 + r]);
            red[r * 4 + qtr] = mx;
        }
        __syncthreads();

        if (tid < 64) {
            float tm = fmaxf(fmaxf(red[tid * 4], red[tid * 4 + 1]),
                             fmaxf(red[tid * 4 + 2], red[tid * 4 + 3]));
            float nm = fmaxf(mrow[tid], tm);
            frow[tid] = __expf(mrow[tid] - nm);
            mrow[tid] = nm;
        }
        __syncthreads();

        // P = exp(S - m) in place; partial row sums
        {
            const int r = tid & 63, qtr = tid >> 6;
            const float nm = mrow[r];
            float sum = 0.f;
#pragma unroll
            for (int t = 0; t < 16; t++) {
                const int idx = (qtr * 16 + t) * 68 + r;
                float p = __expf(Sst[idx] - nm);
                Sst[idx] = p;
                sum += p;
            }
            red[r * 4 + qtr] = sum;
        }
        __syncthreads();

        if (tid < 64)
            lrow[tid] = lrow[tid] * frow[tid] +
                        red[tid * 4] + red[tid * 4 + 1] + red[tid * 4 + 2] + red[tid * 4 + 3];

        // Rescale accumulators, then O += P @ V
        {
            const float f0 = frow[r0], f1 = frow[r0 + 1], f2 = frow[r0 + 2], f3 = frow[r0 + 3];
#pragma unroll
            for (int j = 0; j < 4; j++) {
                o[0][j] *= f0; o[1][j] *= f1; o[2][j] *= f2; o[3][j] *= f3;
            }
#pragma unroll 8
            for (int k = 0; k < 64; k++) {
                float4 p = *(float4*)&Sst[k * 68 + r0];
                float4 v = *(float4*)&KV [k * 68 + c0];
                o[0][0] += p.x * v.x; o[0][1] += p.x * v.y; o[0][2] += p.x * v.z; o[0][3] += p.x * v.w;
                o[1][0] += p.y * v.x; o[1][1] += p.y * v.y; o[1][2] += p.y * v.z; o[1][3] += p.y * v.w;
                o[2][0] += p.z * v.x; o[2][1] += p.z * v.y; o[2][2] += p.z * v.z; o[2][3] += p.z * v.w;
                o[3][0] += p.w * v.x; o[3][1] += p.w * v.y; o[3][2] += p.w * v.z; o[3][3] += p.w * v.w;
            }
        }
        __syncthreads();
    }

    // Write normalized output: g_att[b,n, h*64 + d]
    const int b = bh >> 4, h = bh & 15;
#pragma unroll
    for (int i = 0; i < 4; i++) {
        const int n = q0 + r0 + i;
        const float inv = 1.f / lrow[r0 + i];
        float* dst = &g_att[(b * SEQ + n) * CDIM + h * HDIM + c0];
        dst[0] = o[i][0] * inv;
        dst[1] = o[i][1] * inv;
        dst[2] = o[i][2] * inv;
        dst[3] = o[i][3] * inv;
    }
}

// ---------------------------------------------------------------------------
// Kernel 3: projection GEMM + bias.  g_att[4096,1024] @ Wp[1024,1024] + b.
// ---------------------------------------------------------------------------
__global__ __launch_bounds__(256) void proj_gemm(const float* __restrict__ W,
                                                 const float* __restrict__ bias,
                                                 float* __restrict__ out) {
    __shared__ float As[16][68];
    __shared__ float Bs[16][68];
    const int tid = threadIdx.x;
    const int tx = tid & 15, ty = tid >> 4;
    const int row0 = blockIdx.y * 64;
    const int col0 = blockIdx.x * 64;

    const int am = tid >> 2;
    const int ak = (tid & 3) * 4;
    const int bk = tid >> 4;
    const int bn = (tid & 15) * 4;

    float acc[4][4] = {};

    for (int k0 = 0; k0 < CDIM; k0 += 16) {
        float4 a = *(const float4*)&g_att[(row0 + am) * CDIM + k0 + ak];
        As[ak + 0][am] = a.x; As[ak + 1][am] = a.y;
        As[ak + 2][am] = a.z; As[ak + 3][am] = a.w;
        *(float4*)&Bs[bk][bn] = *(const float4*)&W[(k0 + bk) * CDIM + col0 + bn];
        __syncthreads();
#pragma unroll
        for (int k = 0; k < 16; k++) {
            float4 ra = *(float4*)&As[k][ty * 4];
            float4 rb = *(float4*)&Bs[k][tx * 4];
            acc[0][0] += ra.x * rb.x; acc[0][1] += ra.x * rb.y; acc[0][2] += ra.x * rb.z; acc[0][3] += ra.x * rb.w;
            acc[1][0] += ra.y * rb.x; acc[1][1] += ra.y * rb.y; acc[1][2] += ra.y * rb.z; acc[1][3] += ra.y * rb.w;
            acc[2][0] += ra.z * rb.x; acc[2][1] += ra.z * rb.y; acc[2][2] += ra.z * rb.z; acc[2][3] += ra.z * rb.w;
            acc[3][0] += ra.w * rb.x; acc[3][1] += ra.w * rb.y; acc[3][2] += ra.w * rb.z; acc[3][3] += ra.w * rb.w;
        }
        __syncthreads();
    }

#pragma unroll
    for (int i = 0; i < 4; i++) {
        const int r = row0 + ty * 4 + i;
#pragma unroll
        for (int j = 0; j < 4; j++) {
            const int c = col0 + tx * 4 + j;
            out[r * CDIM + c] = acc[i][j] + bias[c];
        }
    }
}

// ---------------------------------------------------------------------------
extern "C" void kernel_launch(void* const* d_in, const int* in_sizes, int n_in,
                              void* d_out, int out_size) {
    const float* x      = (const float*)d_in[0];
    const float* w_qkv  = (const float*)d_in[1];
    const float* w_proj = (const float*)d_in[2];
    const float* b_proj = (const float*)d_in[3];
    float* out = (float*)d_out;

    (void)in_sizes; (void)n_in; (void)out_size;

    const size_t attn_smem = (3 * 64 * 68 + 3 * 64 + 64 * 4) * sizeof(float);
    cudaFuncSetAttribute(attn_kernel, cudaFuncAttributeMaxDynamicSharedMemorySize,
                         (int)attn_smem);

    qkv_gemm<<<dim3(QKV_N / 64, MROWS / 64), 256>>>(x, w_qkv);
    attn_kernel<<<dim3(SEQ / 64, BATCH * HEADS), 256, attn_smem>>>();
    proj_gemm<<<dim3(CDIM / 64, MROWS / 64), 256>>>(w_proj, b_proj, out);
}

// round 7
// speedup vs baseline: 2.3629x; 2.3629x over previous
#include <cuda_runtime.h>
#include <cstdint>

// Problem constants
#define BATCH 2
#define SEQ   2048
#define CDIM  1024
#define HEADS 16
#define HDIM  64
#define QKV_N (3*CDIM)
#define MROWS (BATCH*SEQ)          // 4096
#define ATT_SCALE 0.125f           // 64^-0.5

// ---------------------------------------------------------------------------
// Scratch (device globals; no allocation allowed)
// ---------------------------------------------------------------------------
__device__ float g_q[BATCH*HEADS*SEQ*HDIM];    // tf32-rounded, pre-scaled
__device__ float g_k[BATCH*HEADS*SEQ*HDIM];    // tf32-rounded
__device__ float g_v[BATCH*HEADS*SEQ*HDIM];    // tf32-rounded
__device__ float g_att[MROWS*CDIM];            // tf32-rounded attention output
__device__ float g_xt[MROWS*CDIM];             // tf32-rounded x
__device__ float g_wqkvt[CDIM*QKV_N];          // tf32-rounded w_qkv
__device__ float g_wpt[CDIM*CDIM];             // tf32-rounded w_proj

// ---------------------------------------------------------------------------
// Helpers
// ---------------------------------------------------------------------------
__device__ __forceinline__ unsigned f2tf32(float f) {
    unsigned u;
    asm("cvt.rna.tf32.f32 %0, %1;" : "=r"(u) : "f"(f));
    return u;
}

// D += A*B, m16n8k8 tf32
__device__ __forceinline__ void mma8(float* c, const unsigned* a, const unsigned* b) {
    asm volatile(
        "mma.sync.aligned.m16n8k8.row.col.f32.tf32.tf32.f32 "
        "{%0,%1,%2,%3}, {%4,%5,%6,%7}, {%8,%9}, {%0,%1,%2,%3};"
        : "+f"(c[0]), "+f"(c[1]), "+f"(c[2]), "+f"(c[3])
        : "r"(a[0]), "r"(a[1]), "r"(a[2]), "r"(a[3]), "r"(b[0]), "r"(b[1]));
}

__device__ __forceinline__ void cp16(unsigned dst, const float* src) {
    asm volatile("cp.async.cg.shared.global [%0], [%1], 16;" :: "r"(dst), "l"(src));
}
#define CP_COMMIT() asm volatile("cp.async.commit_group;")
#define CP_WAIT(N)  asm volatile("cp.async.wait_group %0;" :: "n"(N))

// ---------------------------------------------------------------------------
// Kernel 0: round inputs to tf32 once (x, w_qkv, w_proj)
// ---------------------------------------------------------------------------
#define NX4 (MROWS*CDIM/4)
#define NQ4 (CDIM*QKV_N/4)
#define NP4 (CDIM*CDIM/4)

__global__ __launch_bounds__(256) void cvt3(const float4* __restrict__ x,
                                            const float4* __restrict__ wq,
                                            const float4* __restrict__ wp) {
    int i = blockIdx.x * blockDim.x + threadIdx.x;
    float4 v; float4* dst;
    if (i < NX4)               { v = x[i];             dst = (float4*)g_xt + i; }
    else if (i < NX4+NQ4)      { v = wq[i-NX4];        dst = (float4*)g_wqkvt + (i-NX4); }
    else if (i < NX4+NQ4+NP4)  { v = wp[i-NX4-NQ4];    dst = (float4*)g_wpt + (i-NX4-NQ4); }
    else return;
    v.x = __uint_as_float(f2tf32(v.x));
    v.y = __uint_as_float(f2tf32(v.y));
    v.z = __uint_as_float(f2tf32(v.z));
    v.w = __uint_as_float(f2tf32(v.w));
    *dst = v;
}

// ---------------------------------------------------------------------------
// GEMM: C[M,N] = A[M,K=1024] @ B[K,N], tf32 mma, 128x128x32 tiles,
// 8 warps (2x4), warp tile 64x32 (4x4 m16n8k8), 2-stage cp.async pipeline.
// EPI==0: QKV scatter epilogue.  EPI==1: +bias -> out.
// ---------------------------------------------------------------------------
#define GM_AS (128*36)
#define GM_BS (32*136)
#define GM_STG (GM_AS + GM_BS)
#define GM_SMEM (2*GM_STG*4)

template<int NDIM, int EPI>
__global__ __launch_bounds__(256) void gemm_tf32(const float* __restrict__ bias,
                                                 float* __restrict__ out) {
    extern __shared__ unsigned sh[];
    const float* A  = (EPI == 0) ? g_xt    : g_att;
    const float* Bm = (EPI == 0) ? g_wqkvt : g_wpt;

    const int tid  = threadIdx.x;
    const int lane = tid & 31, warp = tid >> 5;
    const int wm = warp >> 2, wn = warp & 3;          // 2 x 4 warp grid
    const int row0 = blockIdx.y * 128, col0 = blockIdx.x * 128;

    // staging indices
    const int ar = tid >> 1, ac = (tid & 1) * 16;     // A: 128 rows x 32 cols
    const int br = tid >> 3, bc = (tid & 7) * 16;     // B: 32 rows x 128 cols
    const unsigned sb = (unsigned)__cvta_generic_to_shared(sh);

    auto stage = [&](int it, int s) {
        const float* aSrc = A + (row0 + ar) * CDIM + it * 32 + ac;
        unsigned aDst = sb + (s * GM_STG + ar * 36 + ac) * 4;
        const float* bSrc = Bm + (it * 32 + br) * NDIM + col0 + bc;
        unsigned bDst = sb + (s * GM_STG + GM_AS + br * 136 + bc) * 4;
#pragma unroll
        for (int j = 0; j < 4; j++) {
            cp16(aDst + j * 16, aSrc + j * 4);
            cp16(bDst + j * 16, bSrc + j * 4);
        }
    };

    float c[4][4][4] = {};

    stage(0, 0);
    CP_COMMIT();

    const int NK = CDIM / 32;
    const int arow = wm * 64 + (lane >> 2);
    const int bcol = wn * 32 + (lane >> 2);
    for (int it = 0; it < NK; ++it) {
        const int cur = it & 1;
        if (it + 1 < NK) { stage(it + 1, cur ^ 1); CP_COMMIT(); CP_WAIT(1); }
        else             { CP_WAIT(0); }
        __syncthreads();
        const unsigned* as = sh + cur * GM_STG;
        const unsigned* bs = sh + cur * GM_STG + GM_AS;
#pragma unroll
        for (int ks = 0; ks < 4; ++ks) {
            const int kc = ks * 8 + (lane & 3);
            unsigned af[4][4], bf[4][2];
#pragma unroll
            for (int mt = 0; mt < 4; ++mt) {
                const unsigned* p = as + (arow + mt * 16) * 36 + kc;
                af[mt][0] = p[0];        af[mt][1] = p[8 * 36];
                af[mt][2] = p[4];        af[mt][3] = p[8 * 36 + 4];
            }
#pragma unroll
            for (int nt = 0; nt < 4; ++nt) {
                const unsigned* p = bs + kc * 136 + bcol + nt * 8;
                bf[nt][0] = p[0];        bf[nt][1] = p[4 * 136];
            }
#pragma unroll
            for (int mt = 0; mt < 4; ++mt)
#pragma unroll
                for (int nt = 0; nt < 4; ++nt)
                    mma8(c[mt][nt], af[mt], bf[nt]);
        }
        __syncthreads();
    }

    // Epilogue
    if (EPI == 0) {
        const int sel = col0 >> 10;    // uniform per block (128-col tiles, 1024-aligned regions)
#pragma unroll
        for (int mt = 0; mt < 4; ++mt) {
            const int r = row0 + wm * 64 + mt * 16 + (lane >> 2);
#pragma unroll
            for (int nt = 0; nt < 4; ++nt) {
                const int cc = col0 + wn * 32 + nt * 8 + (lane & 3) * 2;
#pragma unroll
                for (int e = 0; e < 4; ++e) {
                    const int rr = r + (e >> 1) * 8;
                    const int cg = cc + (e & 1);
                    const int b = rr >> 11, n = rr & (SEQ - 1);
                    const int rc = cg & (CDIM - 1);
                    const int h = rc >> 6, d = rc & 63;
                    const int idx = ((b * HEADS + h) * SEQ + n) * HDIM + d;
                    const float v = c[mt][nt][e];
                    if (sel == 0)      g_q[idx] = __uint_as_float(f2tf32(v * ATT_SCALE));
                    else if (sel == 1) g_k[idx] = __uint_as_float(f2tf32(v));
                    else               g_v[idx] = __uint_as_float(f2tf32(v));
                }
            }
        }
    } else {
#pragma unroll
        for (int mt = 0; mt < 4; ++mt) {
            const int r = row0 + wm * 64 + mt * 16 + (lane >> 2);
#pragma unroll
            for (int nt = 0; nt < 4; ++nt) {
                const int cc = col0 + wn * 32 + nt * 8 + (lane & 3) * 2;
                const float b0 = __ldg(&bias[cc]), b1 = __ldg(&bias[cc + 1]);
                out[r * CDIM + cc]           = c[mt][nt][0] + b0;
                out[r * CDIM + cc + 1]       = c[mt][nt][1] + b1;
                out[(r + 8) * CDIM + cc]     = c[mt][nt][2] + b0;
                out[(r + 8) * CDIM + cc + 1] = c[mt][nt][3] + b1;
            }
        }
    }
}

// ---------------------------------------------------------------------------
// Flash attention, tf32 mma. 64 queries/block, 64-key tiles, online softmax.
// 8 warps: wm 0..3 (16 q-rows each), wn 0..1 (32 cols each).
// Smem (words): Qs[64][68] @0, Ks[64][68] @4352, Vs[64][72] @8704,
//               Ss[64][68] @13312, mrow/lrow/frow @17664, red @17856.
// ---------------------------------------------------------------------------
#define AT_QS 0
#define AT_KS 4352
#define AT_VS 8704
#define AT_SS 13312
#define AT_MR 17664
#define AT_SMEM ((17856 + 256) * 4)

__global__ __launch_bounds__(256) void attn_tf32() {
    extern __shared__ unsigned sh[];
    unsigned* Qs = sh + AT_QS;
    unsigned* Ks = sh + AT_KS;
    unsigned* Vs = sh + AT_VS;
    float*    Ss = (float*)(sh + AT_SS);
    float*  mrow = (float*)(sh + AT_MR);
    float*  lrow = mrow + 64;
    float*  frow = lrow + 64;
    float*  red  = frow + 64;

    const int tid = threadIdx.x, lane = tid & 31, warp = tid >> 5;
    const int wm = warp >> 1, wn = warp & 1;
    const int bh = blockIdx.y, q0 = blockIdx.x * 64;
    const float* Qg = g_q + (bh * SEQ + q0) * HDIM;
    const float* Kg = g_k + bh * SEQ * HDIM;
    const float* Vg = g_v + bh * SEQ * HDIM;
    const unsigned sb = (unsigned)__cvta_generic_to_shared(sh);

    const int ldr = tid >> 2, ldc = (tid & 3) * 16;   // tile-load mapping

    // Q tile -> smem
    {
        const float* src = Qg + ldr * HDIM + ldc;
        unsigned dst = sb + (AT_QS + ldr * 68 + ldc) * 4;
#pragma unroll
        for (int s = 0; s < 4; ++s) cp16(dst + s * 16, src + s * 4);
        CP_COMMIT();
    }
    if (tid < 64) { mrow[tid] = -1e30f; lrow[tid] = 0.f; }
    CP_WAIT(0);
    __syncthreads();

    // Q fragments in registers for all k-tiles
    unsigned qa[8][4];
    const int r1 = wm * 16 + (lane >> 2);
    {
#pragma unroll
        for (int ks = 0; ks < 8; ++ks) {
            const unsigned* p = Qs + r1 * 68 + ks * 8 + (lane & 3);
            qa[ks][0] = p[0];        qa[ks][1] = p[8 * 68];
            qa[ks][2] = p[4];        qa[ks][3] = p[8 * 68 + 4];
        }
    }

    float o[4][4] = {};
    const int sr = tid >> 2, scg = tid & 3;   // softmax mapping (strided cols)

    for (int kt = 0; kt < SEQ / 64; ++kt) {
        // K,V tiles -> smem (natural layout; cp.async)
        {
            const float* ksrc = Kg + (kt * 64 + ldr) * HDIM + ldc;
            const float* vsrc = Vg + (kt * 64 + ldr) * HDIM + ldc;
            unsigned kd = sb + (AT_KS + ldr * 68 + ldc) * 4;
            unsigned vd = sb + (AT_VS + ldr * 72 + ldc) * 4;
#pragma unroll
            for (int s = 0; s < 4; ++s) {
                cp16(kd + s * 16, ksrc + s * 4);
                cp16(vd + s * 16, vsrc + s * 4);
            }
            CP_COMMIT();
        }
        CP_WAIT(0);
        __syncthreads();

        // S = Q @ K^T
        {
            float s[4][4] = {};
#pragma unroll
            for (int ks = 0; ks < 8; ++ks) {
                const int kc = ks * 8 + (lane & 3);
                unsigned bf[4][2];
#pragma unroll
                for (int nt = 0; nt < 4; ++nt) {
                    const unsigned* p = Ks + (wn * 32 + nt * 8 + (lane >> 2)) * 68 + kc;
                    bf[nt][0] = p[0];  bf[nt][1] = p[4];
                }
#pragma unroll
                for (int nt = 0; nt < 4; ++nt) mma8(s[nt], qa[ks], bf[nt]);
            }
            const int cbase = wn * 32 + (lane & 3) * 2;
#pragma unroll
            for (int nt = 0; nt < 4; ++nt) {
                const int cc = cbase + nt * 8;
                Ss[r1 * 68 + cc]           = s[nt][0];
                Ss[r1 * 68 + cc + 1]       = s[nt][1];
                Ss[(r1 + 8) * 68 + cc]     = s[nt][2];
                Ss[(r1 + 8) * 68 + cc + 1] = s[nt][3];
            }
        }
        __syncthreads();

        // row max (4 threads/row, strided cols)
        {
            float m = -1e30f;
#pragma unroll
            for (int j = 0; j < 16; ++j) m = fmaxf(m, Ss[sr * 68 + scg + j * 4]);
            red[sr * 4 + scg] = m;
        }
        __syncthreads();
        if (tid < 64) {
            float tm = fmaxf(fmaxf(red[tid * 4], red[tid * 4 + 1]),
                             fmaxf(red[tid * 4 + 2], red[tid * 4 + 3]));
            float nm = fmaxf(mrow[tid], tm);
            frow[tid] = __expf(mrow[tid] - nm);
            mrow[tid] = nm;
        }
        __syncthreads();

        // P = exp(S - m); write tf32 bits; partial sums
        {
            const float nm = mrow[sr];
            float sum = 0.f;
#pragma unroll
            for (int j = 0; j < 16; ++j) {
                const int idx = sr * 68 + scg + j * 4;
                float p = __expf(Ss[idx] - nm);
                sum += p;
                Ss[idx] = __uint_as_float(f2tf32(p));
            }
            red[sr * 4 + scg] = sum;
        }
        __syncthreads();
        if (tid < 64)
            lrow[tid] = lrow[tid] * frow[tid] +
                        red[tid * 4] + red[tid * 4 + 1] + red[tid * 4 + 2] + red[tid * 4 + 3];

        // O = O*f + P @ V
        {
            const float f1 = frow[r1], f2 = frow[r1 + 8];
#pragma unroll
            for (int nt = 0; nt < 4; ++nt) {
                o[nt][0] *= f1; o[nt][1] *= f1; o[nt][2] *= f2; o[nt][3] *= f2;
            }
            const unsigned* Sst = (const unsigned*)Ss;
#pragma unroll
            for (int ks = 0; ks < 8; ++ks) {
                const int kc = ks * 8 + (lane & 3);
                unsigned pa[4];
                const unsigned* p = Sst + r1 * 68 + kc;
                pa[0] = p[0];        pa[1] = p[8 * 68];
                pa[2] = p[4];        pa[3] = p[8 * 68 + 4];
#pragma unroll
                for (int nt = 0; nt < 4; ++nt) {
                    unsigned bf[2];
                    const unsigned* q = Vs + kc * 72 + wn * 32 + nt * 8 + (lane >> 2);
                    bf[0] = q[0];    bf[1] = q[4 * 72];
                    mma8(o[nt], pa, bf);
                }
            }
        }
        __syncthreads();
    }

    // Epilogue: normalize, tf32-round, write g_att[b,n, h*64 + d]
    const int b = bh >> 4, h = bh & 15;
    {
        const float i1 = 1.f / lrow[r1], i2 = 1.f / lrow[r1 + 8];
        const int n1 = q0 + r1, n2 = n1 + 8;
#pragma unroll
        for (int nt = 0; nt < 4; ++nt) {
            const int d = h * 64 + wn * 32 + nt * 8 + (lane & 3) * 2;
            float* o1 = &g_att[(b * SEQ + n1) * CDIM + d];
            float* o2 = &g_att[(b * SEQ + n2) * CDIM + d];
            o1[0] = __uint_as_float(f2tf32(o[nt][0] * i1));
            o1[1] = __uint_as_float(f2tf32(o[nt][1] * i1));
            o2[0] = __uint_as_float(f2tf32(o[nt][2] * i2));
            o2[1] = __uint_as_float(f2tf32(o[nt][3] * i2));
        }
    }
}

// ---------------------------------------------------------------------------
extern "C" void kernel_launch(void* const* d_in, const int* in_sizes, int n_in,
                              void* d_out, int out_size) {
    const float* x      = (const float*)d_in[0];
    const float* w_qkv  = (const float*)d_in[1];
    const float* w_proj = (const float*)d_in[2];
    const float* b_proj = (const float*)d_in[3];
    float* out = (float*)d_out;
    (void)in_sizes; (void)n_in; (void)out_size;

    cudaFuncSetAttribute(gemm_tf32<QKV_N, 0>, cudaFuncAttributeMaxDynamicSharedMemorySize, GM_SMEM);
    cudaFuncSetAttribute(gemm_tf32<CDIM, 1>,  cudaFuncAttributeMaxDynamicSharedMemorySize, GM_SMEM);
    cudaFuncSetAttribute(attn_tf32,           cudaFuncAttributeMaxDynamicSharedMemorySize, AT_SMEM);

    const int ncvt = NX4 + NQ4 + NP4;
    cvt3<<<(ncvt + 255) / 256, 256>>>((const float4*)x, (const float4*)w_qkv,
                                      (const float4*)w_proj);
    gemm_tf32<QKV_N, 0><<<dim3(QKV_N / 128, MROWS / 128), 256, GM_SMEM>>>(nullptr, nullptr);
    attn_tf32<<<dim3(SEQ / 64, BATCH * HEADS), 256, AT_SMEM>>>();
    gemm_tf32<CDIM, 1><<<dim3(CDIM / 128, MROWS / 128), 256, GM_SMEM>>>(b_proj, out);
}

// round 8
// speedup vs baseline: 4.3098x; 1.8240x over previous
#include <cuda_runtime.h>
#include <cuda_fp16.h>
#include <cstdint>

// Problem constants
#define BATCH 2
#define SEQ   2048
#define CDIM  1024
#define HEADS 16
#define HDIM  64
#define QKV_N (3*CDIM)
#define MROWS (BATCH*SEQ)          // 4096
#define ATT_SCALE 0.125f           // 64^-0.5

// ---------------------------------------------------------------------------
// Scratch (device globals; no allocation allowed) — all fp16
// ---------------------------------------------------------------------------
__device__ __half g_q[BATCH*HEADS*SEQ*HDIM];    // pre-scaled by ATT_SCALE
__device__ __half g_k[BATCH*HEADS*SEQ*HDIM];
__device__ __half g_v[BATCH*HEADS*SEQ*HDIM];
__device__ __half g_att[MROWS*CDIM];
__device__ __half g_xh[MROWS*CDIM];
__device__ __half g_wqkvh[CDIM*QKV_N];
__device__ __half g_wph[CDIM*CDIM];

// ---------------------------------------------------------------------------
// Helpers
// ---------------------------------------------------------------------------
// D += A*B, m16n8k16 fp16 -> fp32
__device__ __forceinline__ void mma16(float* c, const unsigned* a, const unsigned* b) {
    asm volatile(
        "mma.sync.aligned.m16n8k16.row.col.f32.f16.f16.f32 "
        "{%0,%1,%2,%3}, {%4,%5,%6,%7}, {%8,%9}, {%0,%1,%2,%3};"
        : "+f"(c[0]), "+f"(c[1]), "+f"(c[2]), "+f"(c[3])
        : "r"(a[0]), "r"(a[1]), "r"(a[2]), "r"(a[3]), "r"(b[0]), "r"(b[1]));
}

__device__ __forceinline__ void ldsm4(unsigned* d, unsigned addr) {
    asm volatile("ldmatrix.sync.aligned.m8n8.x4.shared.b16 {%0,%1,%2,%3}, [%4];"
                 : "=r"(d[0]), "=r"(d[1]), "=r"(d[2]), "=r"(d[3]) : "r"(addr));
}
__device__ __forceinline__ void ldsm4t(unsigned* d, unsigned addr) {
    asm volatile("ldmatrix.sync.aligned.m8n8.x4.trans.shared.b16 {%0,%1,%2,%3}, [%4];"
                 : "=r"(d[0]), "=r"(d[1]), "=r"(d[2]), "=r"(d[3]) : "r"(addr));
}

__device__ __forceinline__ void cp16(unsigned dst, const void* src) {
    asm volatile("cp.async.cg.shared.global [%0], [%1], 16;" :: "r"(dst), "l"(src));
}
#define CP_COMMIT() asm volatile("cp.async.commit_group;")
#define CP_WAIT(N)  asm volatile("cp.async.wait_group %0;" :: "n"(N))

// ---------------------------------------------------------------------------
// Kernel 0: convert inputs to fp16 once
// ---------------------------------------------------------------------------
#define NX4 (MROWS*CDIM/4)
#define NQ4 (CDIM*QKV_N/4)
#define NP4 (CDIM*CDIM/4)

__global__ __launch_bounds__(256) void cvt3(const float4* __restrict__ x,
                                            const float4* __restrict__ wq,
                                            const float4* __restrict__ wp) {
    int i = blockIdx.x * blockDim.x + threadIdx.x;
    float4 v; uint2* dst;
    if (i < NX4)               { v = x[i];          dst = (uint2*)g_xh + i; }
    else if (i < NX4+NQ4)      { v = wq[i-NX4];     dst = (uint2*)g_wqkvh + (i-NX4); }
    else if (i < NX4+NQ4+NP4)  { v = wp[i-NX4-NQ4]; dst = (uint2*)g_wph + (i-NX4-NQ4); }
    else return;
    half2 h01 = __floats2half2_rn(v.x, v.y);
    half2 h23 = __floats2half2_rn(v.z, v.w);
    uint2 o;
    o.x = *(unsigned*)&h01; o.y = *(unsigned*)&h23;
    *dst = o;
}

// ---------------------------------------------------------------------------
// GEMM: C[M,N] = A[M,1024] @ B[1024,N], fp16 mma m16n8k16.
// 128x128x64 tiles, 8 warps (2 wm x 4 wn), warp 64x32 (4 mt x 4 nt).
// 2-stage cp.async. EPI==0: QKV scatter. EPI==1: +bias -> fp32 out.
// Smem (bytes): A 128 rows x 144 (128 data + 16 pad); B 64 rows x 272.
// ---------------------------------------------------------------------------
#define GA_STRIDE 144
#define GB_STRIDE 272
#define GA_BYTES (128*GA_STRIDE)          // 18432
#define GB_BYTES (64*GB_STRIDE)           // 17408
#define G_STG (GA_BYTES + GB_BYTES)       // 35840
#define G_SMEM (2*G_STG)                  // 71680

template<int NDIM, int EPI>
__global__ __launch_bounds__(256) void gemm_h(const float* __restrict__ bias,
                                              float* __restrict__ out) {
    extern __shared__ char smem[];
    const __half* A  = (EPI == 0) ? g_xh    : g_att;
    const __half* Bm = (EPI == 0) ? g_wqkvh : g_wph;

    const int tid  = threadIdx.x;
    const int lane = tid & 31, warp = tid >> 5;
    const int wm = warp >> 2, wn = warp & 3;
    const int row0 = blockIdx.y * 128, col0 = blockIdx.x * 128;
    const unsigned sb = (unsigned)__cvta_generic_to_shared(smem);

    // staging: A 128 rows x 128B (2 thr/row, 4x16B each); B 64 rows x 256B (4 thr/row)
    const int arow = tid >> 1, acolh = (tid & 1) * 32;   // halves
    const int brow = tid >> 2, bcolh = (tid & 3) * 32;

    auto stage = [&](int it, int s) {
        const __half* aSrc = A + (size_t)(row0 + arow) * CDIM + it * 64 + acolh;
        unsigned aDst = sb + s * G_STG + arow * GA_STRIDE + acolh * 2;
        const __half* bSrc = Bm + (size_t)(it * 64 + brow) * NDIM + col0 + bcolh;
        unsigned bDst = sb + s * G_STG + GA_BYTES + brow * GB_STRIDE + bcolh * 2;
#pragma unroll
        for (int j = 0; j < 4; j++) {
            cp16(aDst + j * 16, aSrc + j * 8);
            cp16(bDst + j * 16, bSrc + j * 8);
        }
    };

    float c[4][4][4] = {};

    stage(0, 0);
    CP_COMMIT();

    // fragment base addresses (per-thread)
    const unsigned aBase = sb + (wm * 64 + (lane & 15)) * GA_STRIDE + (lane >> 4) * 16;
    const unsigned bBase = sb + GA_BYTES + (lane & 15) * GB_STRIDE
                         + wn * 64 + (lane >> 4) * 16;

    const int NK = CDIM / 64;
    for (int it = 0; it < NK; ++it) {
        const int cur = it & 1;
        if (it + 1 < NK) { stage(it + 1, cur ^ 1); CP_COMMIT(); CP_WAIT(1); }
        else             { CP_WAIT(0); }
        __syncthreads();
        const unsigned so = cur * G_STG;
#pragma unroll
        for (int ks = 0; ks < 4; ++ks) {
            unsigned af[4][4], bf[4][2];
#pragma unroll
            for (int mt = 0; mt < 4; ++mt)
                ldsm4(af[mt], aBase + so + mt * (16 * GA_STRIDE) + ks * 32);
#pragma unroll
            for (int ntp = 0; ntp < 2; ++ntp) {
                unsigned d[4];
                ldsm4t(d, bBase + so + ks * (16 * GB_STRIDE) + ntp * 32);
                bf[2*ntp][0] = d[0];   bf[2*ntp][1] = d[1];
                bf[2*ntp+1][0] = d[2]; bf[2*ntp+1][1] = d[3];
            }
#pragma unroll
            for (int mt = 0; mt < 4; ++mt)
#pragma unroll
                for (int nt = 0; nt < 4; ++nt)
                    mma16(c[mt][nt], af[mt], bf[nt]);
        }
        __syncthreads();
    }

    // Epilogue
    if (EPI == 0) {
        const int sel = col0 >> 10;    // uniform per block
#pragma unroll
        for (int mt = 0; mt < 4; ++mt) {
            const int r = row0 + wm * 64 + mt * 16 + (lane >> 2);
#pragma unroll
            for (int nt = 0; nt < 4; ++nt) {
                const int cc = col0 + wn * 32 + nt * 8 + (lane & 3) * 2;
#pragma unroll
                for (int half_ = 0; half_ < 2; ++half_) {
                    const int rr = r + half_ * 8;
                    const int b = rr >> 11, n = rr & (SEQ - 1);
                    const int rc = cc & (CDIM - 1);
                    const int h = rc >> 6, d = rc & 63;
                    const int idx = ((b * HEADS + h) * SEQ + n) * HDIM + d;
                    float v0 = c[mt][nt][half_ * 2], v1 = c[mt][nt][half_ * 2 + 1];
                    if (sel == 0) {
                        *(half2*)&g_q[idx] = __floats2half2_rn(v0 * ATT_SCALE, v1 * ATT_SCALE);
                    } else if (sel == 1) {
                        *(half2*)&g_k[idx] = __floats2half2_rn(v0, v1);
                    } else {
                        *(half2*)&g_v[idx] = __floats2half2_rn(v0, v1);
                    }
                }
            }
        }
    } else {
#pragma unroll
        for (int mt = 0; mt < 4; ++mt) {
            const int r = row0 + wm * 64 + mt * 16 + (lane >> 2);
#pragma unroll
            for (int nt = 0; nt < 4; ++nt) {
                const int cc = col0 + wn * 32 + nt * 8 + (lane & 3) * 2;
                const float b0 = __ldg(&bias[cc]), b1 = __ldg(&bias[cc + 1]);
                out[r * CDIM + cc]           = c[mt][nt][0] + b0;
                out[r * CDIM + cc + 1]       = c[mt][nt][1] + b1;
                out[(r + 8) * CDIM + cc]     = c[mt][nt][2] + b0;
                out[(r + 8) * CDIM + cc + 1] = c[mt][nt][3] + b1;
            }
        }
    }
}

// ---------------------------------------------------------------------------
// Flash attention fp16 mma. 64 q/block, 64-key tiles, online softmax.
// 8 warps: wm 0..3 (16 q-rows), wn 0..1 (32 cols).
// Smem bytes: Qs@0, Ks@9216, Vs@18432, Ps(half)@27648 (each 64x144),
//             Ss(f32 64x68w)@36864, m/l/f@54272.., red@55040.
// ---------------------------------------------------------------------------
#define AQ_OFF 0
#define AK_OFF 9216
#define AV_OFF 18432
#define AP_OFF 27648
#define AS_OFF 36864
#define AM_OFF 54272
#define AL_OFF 54528
#define AF_OFF 54784
#define AR_OFF 55040
#define AT_SMEM (AR_OFF + 1024)
#define A_STRIDE 144

__global__ __launch_bounds__(256) void attn_h() {
    extern __shared__ char smem[];
    float* Ss   = (float*)(smem + AS_OFF);
    float* mrow = (float*)(smem + AM_OFF);
    float* lrow = (float*)(smem + AL_OFF);
    float* frow = (float*)(smem + AF_OFF);
    float* red  = (float*)(smem + AR_OFF);
    __half* Ph  = (__half*)(smem + AP_OFF);

    const int tid = threadIdx.x, lane = tid & 31, warp = tid >> 5;
    const int wm = warp >> 1, wn = warp & 1;
    const int bh = blockIdx.y, q0 = blockIdx.x * 64;
    const __half* Qg = g_q + (size_t)(bh * SEQ + q0) * HDIM;
    const __half* Kg = g_k + (size_t)bh * SEQ * HDIM;
    const __half* Vg = g_v + (size_t)bh * SEQ * HDIM;
    const unsigned sb = (unsigned)__cvta_generic_to_shared(smem);

    // staging mapping: 64 rows x 128B, 4 thr/row x 2 chunks
    const int ldr = tid >> 2;
    const int ldch = (tid & 3) * 16;          // halves base

    // Q tile -> smem
    {
        const __half* src = Qg + ldr * HDIM + ldch;
        unsigned dst = sb + AQ_OFF + ldr * A_STRIDE + ldch * 2;
        cp16(dst, src); cp16(dst + 16, src + 8);
        CP_COMMIT();
    }
    if (tid < 64) { mrow[tid] = -1e30f; lrow[tid] = 0.f; }
    CP_WAIT(0);
    __syncthreads();

    // Q fragments (all 4 k-steps of d=64)
    unsigned qa[4][4];
    const unsigned qBase = sb + AQ_OFF + (wm * 16 + (lane & 15)) * A_STRIDE + (lane >> 4) * 16;
#pragma unroll
    for (int ks = 0; ks < 4; ++ks) ldsm4(qa[ks], qBase + ks * 32);

    // fragment bases
    const unsigned kBase = sb + AK_OFF + (wn * 32 + (lane & 15)) * A_STRIDE + (lane >> 4) * 16;
    const unsigned vBase = sb + AV_OFF + (lane & 15) * A_STRIDE + wn * 64 + (lane >> 4) * 16;
    const unsigned pBase = sb + AP_OFF + (wm * 16 + (lane & 15)) * A_STRIDE + (lane >> 4) * 16;

    float o[4][4] = {};
    const int r1 = wm * 16 + (lane >> 2);
    const int sr = tid >> 2, scg = tid & 3;

    for (int kt = 0; kt < SEQ / 64; ++kt) {
        // K,V tiles -> smem
        {
            const __half* ksrc = Kg + (size_t)(kt * 64 + ldr) * HDIM + ldch;
            const __half* vsrc = Vg + (size_t)(kt * 64 + ldr) * HDIM + ldch;
            unsigned kd = sb + AK_OFF + ldr * A_STRIDE + ldch * 2;
            unsigned vd = sb + AV_OFF + ldr * A_STRIDE + ldch * 2;
            cp16(kd, ksrc); cp16(kd + 16, ksrc + 8);
            cp16(vd, vsrc); cp16(vd + 16, vsrc + 8);
            CP_COMMIT();
        }
        CP_WAIT(0);
        __syncthreads();

        // S = Q @ K^T
        {
            float s[4][4] = {};
#pragma unroll
            for (int ks = 0; ks < 4; ++ks) {
                unsigned bf[4][2];
#pragma unroll
                for (int ntp = 0; ntp < 2; ++ntp) {
                    unsigned d[4];
                    ldsm4(d, kBase + ntp * (16 * A_STRIDE) + ks * 32);
                    bf[2*ntp][0] = d[0];   bf[2*ntp+1][0] = d[1];
                    bf[2*ntp][1] = d[2];   bf[2*ntp+1][1] = d[3];
                }
#pragma unroll
                for (int nt = 0; nt < 4; ++nt) mma16(s[nt], qa[ks], bf[nt]);
            }
            const int cbase = wn * 32 + (lane & 3) * 2;
#pragma unroll
            for (int nt = 0; nt < 4; ++nt) {
                const int cc = cbase + nt * 8;
                Ss[r1 * 68 + cc]           = s[nt][0];
                Ss[r1 * 68 + cc + 1]       = s[nt][1];
                Ss[(r1 + 8) * 68 + cc]     = s[nt][2];
                Ss[(r1 + 8) * 68 + cc + 1] = s[nt][3];
            }
        }
        __syncthreads();

        // row max
        {
            float m = -1e30f;
#pragma unroll
            for (int j = 0; j < 16; ++j) m = fmaxf(m, Ss[sr * 68 + scg + j * 4]);
            red[sr * 4 + scg] = m;
        }
        __syncthreads();
        if (tid < 64) {
            float tm = fmaxf(fmaxf(red[tid * 4], red[tid * 4 + 1]),
                             fmaxf(red[tid * 4 + 2], red[tid * 4 + 3]));
            float nm = fmaxf(mrow[tid], tm);
            frow[tid] = __expf(mrow[tid] - nm);
            mrow[tid] = nm;
        }
        __syncthreads();

        // P = exp(S - m) -> half smem; partial sums
        {
            const float nm = mrow[sr];
            float sum = 0.f;
#pragma unroll
            for (int j = 0; j < 16; ++j) {
                const int col = scg + j * 4;
                float p = __expf(Ss[sr * 68 + col] - nm);
                sum += p;
                Ph[sr * 72 + col] = __float2half_rn(p);
            }
            red[sr * 4 + scg] = sum;
        }
        __syncthreads();
        if (tid < 64)
            lrow[tid] = lrow[tid] * frow[tid] +
                        red[tid * 4] + red[tid * 4 + 1] + red[tid * 4 + 2] + red[tid * 4 + 3];

        // O = O*f + P @ V
        {
            const float f1 = frow[r1], f2 = frow[r1 + 8];
#pragma unroll
            for (int nt = 0; nt < 4; ++nt) {
                o[nt][0] *= f1; o[nt][1] *= f1; o[nt][2] *= f2; o[nt][3] *= f2;
            }
#pragma unroll
            for (int ks = 0; ks < 4; ++ks) {
                unsigned pa[4];
                ldsm4(pa, pBase + ks * 32);
                unsigned bf[4][2];
#pragma unroll
                for (int ntp = 0; ntp < 2; ++ntp) {
                    unsigned d[4];
                    ldsm4t(d, vBase + ks * (16 * A_STRIDE) + ntp * 32);
                    bf[2*ntp][0] = d[0];   bf[2*ntp][1] = d[1];
                    bf[2*ntp+1][0] = d[2]; bf[2*ntp+1][1] = d[3];
                }
#pragma unroll
                for (int nt = 0; nt < 4; ++nt) mma16(o[nt], pa, bf[nt]);
            }
        }
        __syncthreads();
    }

    // Epilogue: normalize, write half2 to g_att[b,n, h*64 + d]
    const int b = bh >> 4, h = bh & 15;
    {
        const float i1 = 1.f / lrow[r1], i2 = 1.f / lrow[r1 + 8];
        const int n1 = q0 + r1, n2 = n1 + 8;
#pragma unroll
        for (int nt = 0; nt < 4; ++nt) {
            const int d = h * 64 + wn * 32 + nt * 8 + (lane & 3) * 2;
            *(half2*)&g_att[(size_t)(b * SEQ + n1) * CDIM + d] =
                __floats2half2_rn(o[nt][0] * i1, o[nt][1] * i1);
            *(half2*)&g_att[(size_t)(b * SEQ + n2) * CDIM + d] =
                __floats2half2_rn(o[nt][2] * i2, o[nt][3] * i2);
        }
    }
}

// ---------------------------------------------------------------------------
extern "C" void kernel_launch(void* const* d_in, const int* in_sizes, int n_in,
                              void* d_out, int out_size) {
    const float* x      = (const float*)d_in[0];
    const float* w_qkv  = (const float*)d_in[1];
    const float* w_proj = (const float*)d_in[2];
    const float* b_proj = (const float*)d_in[3];
    float* out = (float*)d_out;
    (void)in_sizes; (void)n_in; (void)out_size;

    cudaFuncSetAttribute(gemm_h<QKV_N, 0>, cudaFuncAttributeMaxDynamicSharedMemorySize, G_SMEM);
    cudaFuncSetAttribute(gemm_h<CDIM, 1>,  cudaFuncAttributeMaxDynamicSharedMemorySize, G_SMEM);
    cudaFuncSetAttribute(attn_h,           cudaFuncAttributeMaxDynamicSharedMemorySize, AT_SMEM);

    const int ncvt = NX4 + NQ4 + NP4;
    cvt3<<<(ncvt + 255) / 256, 256>>>((const float4*)x, (const float4*)w_qkv,
                                      (const float4*)w_proj);
    gemm_h<QKV_N, 0><<<dim3(QKV_N / 128, MROWS / 128), 256, G_SMEM>>>(nullptr, nullptr);
    attn_h<<<dim3(SEQ / 64, BATCH * HEADS), 256, AT_SMEM>>>();
    gemm_h<CDIM, 1><<<dim3(CDIM / 128, MROWS / 128), 256, G_SMEM>>>(b_proj, out);
}

// round 10
// speedup vs baseline: 6.9241x; 1.6066x over previous
#include <cuda_runtime.h>
#include <cuda_fp16.h>
#include <cstdint>

// Problem constants
#define BATCH 2
#define SEQ   2048
#define CDIM  1024
#define HEADS 16
#define HDIM  64
#define QKV_N (3*CDIM)
#define MROWS (BATCH*SEQ)          // 4096
#define ATT_SCALE 0.125f           // 64^-0.5

// ---------------------------------------------------------------------------
// Scratch (device globals) — fp16
// ---------------------------------------------------------------------------
__device__ __half g_q[BATCH*HEADS*SEQ*HDIM];    // pre-scaled by ATT_SCALE
__device__ __half g_k[BATCH*HEADS*SEQ*HDIM];
__device__ __half g_v[BATCH*HEADS*SEQ*HDIM];
__device__ __half g_att[MROWS*CDIM];
__device__ __half g_xh[MROWS*CDIM];
__device__ __half g_wqkvh[CDIM*QKV_N];
__device__ __half g_wph[CDIM*CDIM];

// ---------------------------------------------------------------------------
// Helpers
// ---------------------------------------------------------------------------
__device__ __forceinline__ void mma16(float* c, const unsigned* a, const unsigned* b) {
    asm volatile(
        "mma.sync.aligned.m16n8k16.row.col.f32.f16.f16.f32 "
        "{%0,%1,%2,%3}, {%4,%5,%6,%7}, {%8,%9}, {%0,%1,%2,%3};"
        : "+f"(c[0]), "+f"(c[1]), "+f"(c[2]), "+f"(c[3])
        : "r"(a[0]), "r"(a[1]), "r"(a[2]), "r"(a[3]), "r"(b[0]), "r"(b[1]));
}
__device__ __forceinline__ void ldsm4(unsigned* d, unsigned addr) {
    asm volatile("ldmatrix.sync.aligned.m8n8.x4.shared.b16 {%0,%1,%2,%3}, [%4];"
                 : "=r"(d[0]), "=r"(d[1]), "=r"(d[2]), "=r"(d[3]) : "r"(addr));
}
__device__ __forceinline__ void ldsm4t(unsigned* d, unsigned addr) {
    asm volatile("ldmatrix.sync.aligned.m8n8.x4.trans.shared.b16 {%0,%1,%2,%3}, [%4];"
                 : "=r"(d[0]), "=r"(d[1]), "=r"(d[2]), "=r"(d[3]) : "r"(addr));
}
__device__ __forceinline__ void cp16(unsigned dst, const void* src) {
    asm volatile("cp.async.cg.shared.global [%0], [%1], 16;" :: "r"(dst), "l"(src));
}
#define CP_COMMIT() asm volatile("cp.async.commit_group;")
#define CP_WAIT(N)  asm volatile("cp.async.wait_group %0;" :: "n"(N))

__device__ __forceinline__ unsigned h2u(float a, float b) {
    half2 h = __floats2half2_rn(a, b);
    return *(unsigned*)&h;
}

// ---------------------------------------------------------------------------
// Kernel 0: convert inputs to fp16 once
// ---------------------------------------------------------------------------
#define NX4 (MROWS*CDIM/4)
#define NQ4 (CDIM*QKV_N/4)
#define NP4 (CDIM*CDIM/4)

__global__ __launch_bounds__(256) void cvt3(const float4* __restrict__ x,
                                            const float4* __restrict__ wq,
                                            const float4* __restrict__ wp) {
    int i = blockIdx.x * blockDim.x + threadIdx.x;
    float4 v; uint2* dst;
    if (i < NX4)               { v = x[i];          dst = (uint2*)g_xh + i; }
    else if (i < NX4+NQ4)      { v = wq[i-NX4];     dst = (uint2*)g_wqkvh + (i-NX4); }
    else if (i < NX4+NQ4+NP4)  { v = wp[i-NX4-NQ4]; dst = (uint2*)g_wph + (i-NX4-NQ4); }
    else return;
    uint2 o;
    o.x = h2u(v.x, v.y); o.y = h2u(v.z, v.w);
    *dst = o;
}

// ---------------------------------------------------------------------------
// GEMM: C[M,N] = A[M,1024] @ B[1024,N], fp16 mma m16n8k16.
// 128x128 tiles, BK=32, 4-stage cp.async pipeline, 8 warps (2x4), warp 64x32.
// EPI==0: QKV scatter.  EPI==1: +bias -> fp32 out.
// ---------------------------------------------------------------------------
#define GA_STRIDE 80                       // 64B data + 16 pad
#define GB_STRIDE 272                      // 256B data + 16 pad
#define GA_BYTES (128*GA_STRIDE)           // 10240
#define GB_BYTES (32*GB_STRIDE)            // 8704
#define G_STG    (GA_BYTES + GB_BYTES)     // 18944
#define G_STAGES 4
#define G_SMEM   (G_STAGES*G_STG)          // 75776

template<int NDIM, int EPI>
__global__ __launch_bounds__(256) void gemm_h(const float* __restrict__ bias,
                                              float* __restrict__ out) {
    extern __shared__ char smem[];
    const __half* A  = (EPI == 0) ? g_xh    : g_att;
    const __half* Bm = (EPI == 0) ? g_wqkvh : g_wph;

    const int tid  = threadIdx.x;
    const int lane = tid & 31, warp = tid >> 5;
    const int wm = warp >> 2, wn = warp & 3;
    const int row0 = blockIdx.y * 128, col0 = blockIdx.x * 128;
    const unsigned sb = (unsigned)__cvta_generic_to_shared(smem);

    // staging: A 128 rows x 64B (2 thr/row); B 32 rows x 256B (8 thr/row)
    const int arow = tid >> 1, acolh = (tid & 1) * 16;
    const int brow = tid >> 3, bcolh = (tid & 7) * 16;

    auto stage = [&](int it, int s) {
        const __half* aSrc = A + (size_t)(row0 + arow) * CDIM + it * 32 + acolh;
        unsigned aDst = sb + s * G_STG + arow * GA_STRIDE + acolh * 2;
        cp16(aDst, aSrc); cp16(aDst + 16, aSrc + 8);
        const __half* bSrc = Bm + (size_t)(it * 32 + brow) * NDIM + col0 + bcolh;
        unsigned bDst = sb + s * G_STG + GA_BYTES + brow * GB_STRIDE + bcolh * 2;
        cp16(bDst, bSrc); cp16(bDst + 16, bSrc + 8);
    };

    float c[4][4][4] = {};

    stage(0, 0); CP_COMMIT();
    stage(1, 1); CP_COMMIT();
    stage(2, 2); CP_COMMIT();

    const unsigned aBase = sb + (wm * 64 + (lane & 15)) * GA_STRIDE + (lane >> 4) * 16;
    const unsigned bBase = sb + GA_BYTES + (lane & 15) * GB_STRIDE
                         + wn * 64 + (lane >> 4) * 16;

    const int NK = CDIM / 32;
    for (int it = 0; it < NK; ++it) {
        CP_WAIT(2);
        __syncthreads();
        if (it + 3 < NK) stage(it + 3, (it + 3) & 3);
        CP_COMMIT();

        const unsigned so = (it & 3) * G_STG;
#pragma unroll
        for (int ks = 0; ks < 2; ++ks) {
            unsigned af[4][4], bf[4][2];
#pragma unroll
            for (int mt = 0; mt < 4; ++mt)
                ldsm4(af[mt], aBase + so + mt * (16 * GA_STRIDE) + ks * 32);
#pragma unroll
            for (int ntp = 0; ntp < 2; ++ntp) {
                unsigned d4[4];
                ldsm4t(d4, bBase + so + ks * (16 * GB_STRIDE) + ntp * 32);
                bf[2*ntp][0] = d4[0];   bf[2*ntp][1] = d4[1];
                bf[2*ntp+1][0] = d4[2]; bf[2*ntp+1][1] = d4[3];
            }
#pragma unroll
            for (int mt = 0; mt < 4; ++mt)
#pragma unroll
                for (int nt = 0; nt < 4; ++nt)
                    mma16(c[mt][nt], af[mt], bf[nt]);
        }
    }

    // Epilogue
    if (EPI == 0) {
        const int sel = col0 >> 10;    // uniform per block
#pragma unroll
        for (int mt = 0; mt < 4; ++mt) {
            const int r = row0 + wm * 64 + mt * 16 + (lane >> 2);
#pragma unroll
            for (int nt = 0; nt < 4; ++nt) {
                const int cc = col0 + wn * 32 + nt * 8 + (lane & 3) * 2;
#pragma unroll
                for (int hf = 0; hf < 2; ++hf) {
                    const int rr = r + hf * 8;
                    const int b = rr >> 11, n = rr & (SEQ - 1);
                    const int rc = cc & (CDIM - 1);
                    const int h = rc >> 6, d = rc & 63;
                    const int idx = ((b * HEADS + h) * SEQ + n) * HDIM + d;
                    float v0 = c[mt][nt][hf * 2], v1 = c[mt][nt][hf * 2 + 1];
                    if (sel == 0)
                        *(half2*)&g_q[idx] = __floats2half2_rn(v0 * ATT_SCALE, v1 * ATT_SCALE);
                    else if (sel == 1)
                        *(half2*)&g_k[idx] = __floats2half2_rn(v0, v1);
                    else
                        *(half2*)&g_v[idx] = __floats2half2_rn(v0, v1);
                }
            }
        }
    } else {
#pragma unroll
        for (int mt = 0; mt < 4; ++mt) {
            const int r = row0 + wm * 64 + mt * 16 + (lane >> 2);
#pragma unroll
            for (int nt = 0; nt < 4; ++nt) {
                const int cc = col0 + wn * 32 + nt * 8 + (lane & 3) * 2;
                const float b0 = __ldg(&bias[cc]), b1 = __ldg(&bias[cc + 1]);
                out[r * CDIM + cc]           = c[mt][nt][0] + b0;
                out[r * CDIM + cc + 1]       = c[mt][nt][1] + b1;
                out[(r + 8) * CDIM + cc]     = c[mt][nt][2] + b0;
                out[(r + 8) * CDIM + cc + 1] = c[mt][nt][3] + b1;
            }
        }
    }
}

// ---------------------------------------------------------------------------
// FlashAttention-2, register-resident softmax. 128 q/block, 64-key tiles.
// 8 warps, each owns m16 x n64 stripe. S/P in registers; quad shuffles for
// row stats; P fragments reused directly as A operand for PV.
// Smem: Q 128x144B @0; K/V double buffer: stage s at 18432 + s*18432
//       (K at +0, V at +9216), each 64x144B.
// ---------------------------------------------------------------------------
#define AQ_OFF  0
#define AKV_OFF 18432
#define KV_HALF 9216
#define KV_STG  18432
#define AT_SMEM (AKV_OFF + 2*KV_STG)       // 55296
#define A_STRIDE 144

__global__ __launch_bounds__(256) void attn_fa2() {
    extern __shared__ char smem[];
    const int tid = threadIdx.x, lane = tid & 31, wm = tid >> 5;
    const int bh = blockIdx.y, q0 = blockIdx.x * 128;
    const __half* Qg = g_q + (size_t)(bh * SEQ + q0) * HDIM;
    const __half* Kg = g_k + (size_t)bh * SEQ * HDIM;
    const __half* Vg = g_v + (size_t)bh * SEQ * HDIM;
    const unsigned sb = (unsigned)__cvta_generic_to_shared(smem);

    // ---- stage Q (128 rows x 128B; 2 thr/row) ----
    {
        const int r = tid >> 1, ch = (tid & 1) * 32;
        const __half* src = Qg + r * HDIM + ch;
        unsigned dst = sb + AQ_OFF + r * A_STRIDE + ch * 2;
        cp16(dst, src);      cp16(dst + 16, src + 8);
        cp16(dst + 32, src + 16); cp16(dst + 48, src + 24);
    }
    // ---- stage K/V tile 0 (64 rows x 128B; 4 thr/row) ----
    const int ldr = tid >> 2, ldch = (tid & 3) * 16;
    auto stageKV = [&](int kt, int s) {
        const __half* ksrc = Kg + (size_t)(kt * 64 + ldr) * HDIM + ldch;
        const __half* vsrc = Vg + (size_t)(kt * 64 + ldr) * HDIM + ldch;
        unsigned kd = sb + AKV_OFF + s * KV_STG + ldr * A_STRIDE + ldch * 2;
        unsigned vd = kd + KV_HALF;
        cp16(kd, ksrc); cp16(kd + 16, ksrc + 8);
        cp16(vd, vsrc); cp16(vd + 16, vsrc + 8);
    };
    stageKV(0, 0);
    CP_COMMIT();
    CP_WAIT(0);
    __syncthreads();

    // ---- Q fragments (m16 x k64 per warp) ----
    unsigned qa[4][4];
    const unsigned qBase = sb + AQ_OFF + (wm * 16 + (lane & 15)) * A_STRIDE + (lane >> 4) * 16;
#pragma unroll
    for (int ks = 0; ks < 4; ++ks) ldsm4(qa[ks], qBase + ks * 32);

    const unsigned kBase = sb + AKV_OFF + (lane & 15) * A_STRIDE + (lane >> 4) * 16;
    const unsigned vBase = kBase + KV_HALF;

    float o[8][4] = {};
    float m0 = -1e30f, m1 = -1e30f, l0 = 0.f, l1 = 0.f;

    const int NT = SEQ / 64;
    for (int it = 0; it < NT; ++it) {
        if (it > 0) { CP_WAIT(0); __syncthreads(); }
        if (it + 1 < NT) stageKV(it + 1, (it + 1) & 1);
        CP_COMMIT();
        const unsigned so = (it & 1) * KV_STG;

        // ---- S = Q @ K^T  (m16 x n64 in registers) ----
        float s[8][4] = {};
#pragma unroll
        for (int ks = 0; ks < 4; ++ks) {
            unsigned bf[8][2];
#pragma unroll
            for (int np = 0; np < 4; ++np) {
                unsigned d4[4];
                ldsm4(d4, kBase + so + np * (16 * A_STRIDE) + ks * 32);
                bf[2*np][0] = d4[0];   bf[2*np+1][0] = d4[1];
                bf[2*np][1] = d4[2];   bf[2*np+1][1] = d4[3];
            }
#pragma unroll
            for (int j = 0; j < 8; ++j) mma16(s[j], qa[ks], bf[j]);
        }

        // ---- online softmax (registers + quad shuffles) ----
        float mx0 = -1e30f, mx1 = -1e30f;
#pragma unroll
        for (int j = 0; j < 8; ++j) {
            mx0 = fmaxf(mx0, fmaxf(s[j][0], s[j][1]));
            mx1 = fmaxf(mx1, fmaxf(s[j][2], s[j][3]));
        }
        mx0 = fmaxf(mx0, __shfl_xor_sync(0xffffffffu, mx0, 1));
        mx0 = fmaxf(mx0, __shfl_xor_sync(0xffffffffu, mx0, 2));
        mx1 = fmaxf(mx1, __shfl_xor_sync(0xffffffffu, mx1, 1));
        mx1 = fmaxf(mx1, __shfl_xor_sync(0xffffffffu, mx1, 2));
        const float nm0 = fmaxf(m0, mx0), nm1 = fmaxf(m1, mx1);
        const float f0 = __expf(m0 - nm0), f1 = __expf(m1 - nm1);
        m0 = nm0; m1 = nm1;

        float sum0 = 0.f, sum1 = 0.f;
        unsigned pa[4][4];
#pragma unroll
        for (int t = 0; t < 4; ++t) {
            float p00 = __expf(s[2*t][0]   - m0), p01 = __expf(s[2*t][1]   - m0);
            float p02 = __expf(s[2*t][2]   - m1), p03 = __expf(s[2*t][3]   - m1);
            float p10 = __expf(s[2*t+1][0] - m0), p11 = __expf(s[2*t+1][1] - m0);
            float p12 = __expf(s[2*t+1][2] - m1), p13 = __expf(s[2*t+1][3] - m1);
            sum0 += p00 + p01 + p10 + p11;
            sum1 += p02 + p03 + p12 + p13;
            pa[t][0] = h2u(p00, p01);
            pa[t][1] = h2u(p02, p03);
            pa[t][2] = h2u(p10, p11);
            pa[t][3] = h2u(p12, p13);
        }
        sum0 += __shfl_xor_sync(0xffffffffu, sum0, 1);
        sum0 += __shfl_xor_sync(0xffffffffu, sum0, 2);
        sum1 += __shfl_xor_sync(0xffffffffu, sum1, 1);
        sum1 += __shfl_xor_sync(0xffffffffu, sum1, 2);
        l0 = l0 * f0 + sum0;
        l1 = l1 * f1 + sum1;

        // ---- O = O*f + P @ V ----
#pragma unroll
        for (int j = 0; j < 8; ++j) {
            o[j][0] *= f0; o[j][1] *= f0; o[j][2] *= f1; o[j][3] *= f1;
        }
#pragma unroll
        for (int t = 0; t < 4; ++t) {
            unsigned bf[8][2];
#pragma unroll
            for (int np = 0; np < 4; ++np) {
                unsigned d4[4];
                ldsm4t(d4, vBase + so + t * (16 * A_STRIDE) + np * 32);
                bf[2*np][0] = d4[0];   bf[2*np][1] = d4[1];
                bf[2*np+1][0] = d4[2]; bf[2*np+1][1] = d4[3];
            }
#pragma unroll
            for (int j = 0; j < 8; ++j) mma16(o[j], pa[t], bf[j]);
        }
    }

    // ---- epilogue: normalize, write half2 to g_att[b, n, h*64 + d] ----
    const int b = bh >> 4, h = bh & 15;
    const int r1 = wm * 16 + (lane >> 2);
    const float i0 = 1.f / l0, i1 = 1.f / l1;
    const int n1 = q0 + r1, n2 = n1 + 8;
#pragma unroll
    for (int j = 0; j < 8; ++j) {
        const int d = h * 64 + j * 8 + (lane & 3) * 2;
        *(half2*)&g_att[(size_t)(b * SEQ + n1) * CDIM + d] =
            __floats2half2_rn(o[j][0] * i0, o[j][1] * i0);
        *(half2*)&g_att[(size_t)(b * SEQ + n2) * CDIM + d] =
            __floats2half2_rn(o[j][2] * i1, o[j][3] * i1);
    }
}

// ---------------------------------------------------------------------------
extern "C" void kernel_launch(void* const* d_in, const int* in_sizes, int n_in,
                              void* d_out, int out_size) {
    const float* x      = (const float*)d_in[0];
    const float* w_qkv  = (const float*)d_in[1];
    const float* w_proj = (const float*)d_in[2];
    const float* b_proj = (const float*)d_in[3];
    float* out = (float*)d_out;
    (void)in_sizes; (void)n_in; (void)out_size;

    cudaFuncSetAttribute(gemm_h<QKV_N, 0>, cudaFuncAttributeMaxDynamicSharedMemorySize, G_SMEM);
    cudaFuncSetAttribute(gemm_h<CDIM, 1>,  cudaFuncAttributeMaxDynamicSharedMemorySize, G_SMEM);
    cudaFuncSetAttribute(attn_fa2,         cudaFuncAttributeMaxDynamicSharedMemorySize, AT_SMEM);

    const int ncvt = NX4 + NQ4 + NP4;
    cvt3<<<(ncvt + 255) / 256, 256>>>((const float4*)x, (const float4*)w_qkv,
                                      (const float4*)w_proj);
    gemm_h<QKV_N, 0><<<dim3(QKV_N / 128, MROWS / 128), 256, G_SMEM>>>(nullptr, nullptr);
    attn_fa2<<<dim3(SEQ / 128, BATCH * HEADS), 256, AT_SMEM>>>();
    gemm_h<CDIM, 1><<<dim3(CDIM / 128, MROWS / 128), 256, G_SMEM>>>(b_proj, out);
}